// round 6
// baseline (speedup 1.0000x reference)
#include <cuda_runtime.h>

#define T_STEPS 512
#define BATCH   2048
#define IN_DIM  28
#define HID     198
#define OUT_DIM 10

#define BBLK     16
#define NBLOCKS  (BATCH / BBLK)   // 128
#define NTHREADS 256

#define KPAD 200                  // k padded to 200 (50 exact float4 quads), pad = 0
#define HSTR 204                  // H_s / h_s row stride in floats (204 mod 32 = 12 -> conflict-free LDS.128)
#define USTR 36                   // U_s row stride (36 mod 32 = 4 -> conflict-free LDS.128)
#define XSTR 32                   // x_s row stride

// shared memory layout (in floats)
#define H_S_OFF   0
#define U_S_OFF   (HID * HSTR)                 // 40392
#define HST_S_OFF (U_S_OFF + HID * USTR)       // + 7128  = 47520 (hidden state)
#define X_S_OFF   (HST_S_OFF + BBLK * HSTR)    // + 3264  = 50784
#define B_S_OFF   (X_S_OFF + BBLK * XSTR)      // + 512   = 51296
#define SMEM_FLOATS (B_S_OFF + KPAD)           // 51496 -> 205984 bytes

// Per-step fused GEMM:  acc[r][m] = b[j] + sum_k x[bb][k]*U[k][j] + sum_k h[bb][k]*H[j][k]
// Thread tile: 4 batch rows (r) x NJ j-columns (m), j = jl + 64*m (clamped; invalid slots
// compute garbage into unstored accumulators).
template<int NJ>
__device__ __forceinline__ void step_gemm(
    float (&acc)[4][4],
    const float* __restrict__ sm_H, const float* __restrict__ sm_U,
    const float* __restrict__ sm_h, const float* __restrict__ sm_x,
    const float* __restrict__ sm_b,
    int bb0, int jl)
{
    int jj[NJ];
#pragma unroll
    for (int m = 0; m < NJ; m++) {
        int j = jl + 64 * m;
        jj[m] = (j < HID) ? j : 0;          // clamp keeps smem reads in-bounds
    }

#pragma unroll
    for (int r = 0; r < 4; r++)
#pragma unroll
        for (int m = 0; m < NJ; m++)
            acc[r][m] = sm_b[jj[m]];

    // input projection part: K = 28 -> 7 exact quads
#pragma unroll
    for (int kq = 0; kq < IN_DIM / 4; kq++) {
        float4 xv[4];
#pragma unroll
        for (int r = 0; r < 4; r++)
            xv[r] = *reinterpret_cast<const float4*>(sm_x + (bb0 + r) * XSTR + kq * 4);
#pragma unroll
        for (int m = 0; m < NJ; m++) {
            float4 uv = *reinterpret_cast<const float4*>(sm_U + jj[m] * USTR + kq * 4);
#pragma unroll
            for (int r = 0; r < 4; r++) {
                acc[r][m] += xv[r].x * uv.x;
                acc[r][m] += xv[r].y * uv.y;
                acc[r][m] += xv[r].z * uv.z;
                acc[r][m] += xv[r].w * uv.w;
            }
        }
    }

    // recurrent part: K padded to 200 -> 50 exact quads (pad columns are zero)
#pragma unroll 5
    for (int kq = 0; kq < KPAD / 4; kq++) {
        float4 hv[4];
#pragma unroll
        for (int r = 0; r < 4; r++)
            hv[r] = *reinterpret_cast<const float4*>(sm_h + (bb0 + r) * HSTR + kq * 4);
#pragma unroll
        for (int m = 0; m < NJ; m++) {
            float4 wv = *reinterpret_cast<const float4*>(sm_H + jj[m] * HSTR + kq * 4);
#pragma unroll
            for (int r = 0; r < 4; r++) {
                acc[r][m] += hv[r].x * wv.x;
                acc[r][m] += hv[r].y * wv.y;
                acc[r][m] += hv[r].z * wv.z;
                acc[r][m] += hv[r].w * wv.w;
            }
        }
    }
}

__global__ __launch_bounds__(NTHREADS, 1)
void SimpleRNN_kernel(const float* __restrict__ x, const float* __restrict__ H,
                      const float* __restrict__ U, const float* __restrict__ A,
                      const float* __restrict__ bvec, const float* __restrict__ cvec,
                      float* __restrict__ out)
{
    extern __shared__ float sm[];
    float* sm_H = sm + H_S_OFF;
    float* sm_U = sm + U_S_OFF;
    float* sm_h = sm + HST_S_OFF;
    float* sm_x = sm + X_S_OFF;
    float* sm_b = sm + B_S_OFF;

    const int tid = threadIdx.x;
    const int b0  = blockIdx.x * BBLK;

    // ---- one-time weight staging ----
    for (int i = tid; i < HID * HSTR; i += NTHREADS) {
        int j = i / HSTR, k = i - j * HSTR;
        sm_H[i] = (k < HID) ? H[j * HID + k] : 0.f;       // H[j][k], k-padded with zeros
    }
    for (int i = tid; i < HID * USTR; i += NTHREADS) {
        int j = i / USTR, k = i - j * USTR;
        sm_U[i] = (k < IN_DIM) ? U[k * HID + j] : 0.f;    // transposed: U_s[j][k]
    }
    for (int i = tid; i < KPAD; i += NTHREADS)
        sm_b[i] = (i < HID) ? bvec[i] : 0.f;
    for (int i = tid; i < BBLK * HSTR; i += NTHREADS)
        sm_h[i] = 0.f;                                     // h0 = 0 (pad cols stay 0 forever)
    __syncthreads();

    const int  jl   = tid & 63;          // j lane 0..63
    const int  bb0  = (tid >> 6) * 4;    // batch-row group base 0,4,8,12
    const bool has4 = (jl < 32);         // warp-uniform: first warp of each group carries j-tail

    for (int t = 0; t < T_STEPS; t++) {
        // stage x[t, b0:b0+16, :] (contiguous 448 floats)
        const float* gx = x + (size_t)t * (BATCH * IN_DIM) + (size_t)b0 * IN_DIM;
        for (int i = tid; i < BBLK * IN_DIM; i += NTHREADS) {
            int bb = i / IN_DIM;
            int k  = i - bb * IN_DIM;
            sm_x[bb * XSTR + k] = gx[i];
        }
        __syncthreads();   // x_s ready; previous h_s writes visible

        float acc[4][4];
        if (has4) step_gemm<4>(acc, sm_H, sm_U, sm_h, sm_x, sm_b, bb0, jl);
        else      step_gemm<3>(acc, sm_H, sm_U, sm_h, sm_x, sm_b, bb0, jl);

        __syncthreads();   // all reads of h_s done before overwrite

#pragma unroll
        for (int r = 0; r < 4; r++) {
            float* hrow = sm_h + (bb0 + r) * HSTR;
#pragma unroll
            for (int m = 0; m < 3; m++)
                hrow[jl + 64 * m] = tanhf(acc[r][m]);
        }
        if (jl + 192 < HID) {            // only lanes 0..5 of has4 warps
#pragma unroll
            for (int r = 0; r < 4; r++)
                sm_h[(bb0 + r) * HSTR + jl + 192] = tanhf(acc[r][3]);
        }
    }
    __syncthreads();

    // ---- output projection: out[b][o] = h[b] . A[o] + c[o]  (16 x 10 per block) ----
    if (tid < BBLK * OUT_DIM) {
        int bb = tid / OUT_DIM;
        int o  = tid - bb * OUT_DIM;
        float s = cvec[o];
        const float* hrow = sm_h + bb * HSTR;
        const float* arow = A + o * HID;
#pragma unroll 4
        for (int j = 0; j < HID; j++)
            s += hrow[j] * arow[j];
        out[(b0 + bb) * OUT_DIM + o] = s;
    }
}

extern "C" void kernel_launch(void* const* d_in, const int* in_sizes, int n_in,
                              void* d_out, int out_size)
{
    // identify inputs by element count (all distinct): robust to ordering
    const float *x = nullptr, *H = nullptr, *U = nullptr, *A = nullptr, *b = nullptr, *c = nullptr;
    for (int i = 0; i < n_in; i++) {
        const float* p = (const float*)d_in[i];
        switch (in_sizes[i]) {
            case T_STEPS * BATCH * IN_DIM: x = p; break;   // 29,360,128
            case HID * HID:                H = p; break;   // 39,204
            case IN_DIM * HID:             U = p; break;   // 5,544
            case OUT_DIM * HID:            A = p; break;   // 1,980
            case HID:                      b = p; break;   // 198
            case OUT_DIM:                  c = p; break;   // 10
            default: break;
        }
    }
    float* out = (float*)d_out;

    size_t smem_bytes = SMEM_FLOATS * sizeof(float);   // 205,984 B (< 227 KB limit)
    cudaFuncSetAttribute(SimpleRNN_kernel,
                         cudaFuncAttributeMaxDynamicSharedMemorySize, (int)smem_bytes);

    SimpleRNN_kernel<<<NBLOCKS, NTHREADS, smem_bytes>>>(x, H, U, A, b, c, out);
}

// round 7
// speedup vs baseline: 1.0814x; 1.0814x over previous
#include <cuda_runtime.h>

#define T_STEPS 512
#define BATCH   2048
#define IN_DIM  28
#define HID     198
#define OUT_DIM 10

#define BBLK     16
#define NBLOCKS  (BATCH / BBLK)   // 128
#define NTHREADS 256

#define KPAD 200                  // recurrent k padded to 200 (50 exact float4 quads), pad = 0
#define HSTR 204                  // H_s / h_s row stride (204 mod 32 = 12 -> 8 rows hit 32 distinct banks)
#define USTR 36                   // U_s / x_s row stride (36 mod 32 = 4 -> conflict-free)

// shared layout (floats)
#define H_S_OFF   0
#define U_S_OFF   (HID * HSTR)                 // 40392
#define HST_S_OFF (U_S_OFF + HID * USTR)       // 47520
#define X_S_OFF   (HST_S_OFF + BBLK * HSTR)    // 50784
#define SMEM_FLOATS (X_S_OFF + BBLK * USTR)    // 51360 -> 205,440 bytes

// packed dual-fp32 FMA: d.lo += a.lo*b.lo ; d.hi += a.hi*b.hi   (sm_100+ PTX)
__device__ __forceinline__ void fma2(unsigned long long& d,
                                     unsigned long long a,
                                     unsigned long long b) {
    asm("fma.rn.f32x2 %0, %1, %2, %0;" : "+l"(d) : "l"(a), "l"(b));
}

__global__ __launch_bounds__(NTHREADS, 1)
void SimpleRNN_kernel(const float* __restrict__ x, const float* __restrict__ H,
                      const float* __restrict__ U, const float* __restrict__ A,
                      const float* __restrict__ bvec, const float* __restrict__ cvec,
                      float* __restrict__ out)
{
    extern __shared__ float sm[];
    float* sm_H = sm + H_S_OFF;    // [HID][HSTR], k-cols 198..203 zero
    float* sm_U = sm + U_S_OFF;    // [HID][USTR] transposed U, k-cols 28..35 zero
    float* sm_h = sm + HST_S_OFF;  // [16][HSTR], k-cols 198..203 stay zero forever
    float* sm_x = sm + X_S_OFF;    // [16][USTR]

    const int tid = threadIdx.x;
    const int b0  = blockIdx.x * BBLK;

    // ---- one-time weight staging ----
    for (int i = tid; i < HID * HSTR; i += NTHREADS) {
        int j = i / HSTR, k = i - j * HSTR;
        sm_H[i] = (k < HID) ? H[j * HID + k] : 0.f;
    }
    for (int i = tid; i < HID * USTR; i += NTHREADS) {
        int j = i / USTR, k = i - j * USTR;
        sm_U[i] = (k < IN_DIM) ? U[k * HID + j] : 0.f;
    }
    for (int i = tid; i < BBLK * HSTR; i += NTHREADS)
        sm_h[i] = 0.f;                                 // h0 = 0

    // ---- lane decomposition: 8 row-lanes (u) x 4 j-lanes (v) per warp ----
    // thread tile: rows {u, u+8} x 7 j-values j = wid*28 + 4m + v  (j in [0,224), clamp >=198)
    const int wid  = tid >> 5;
    const int lane = tid & 31;
    const int u    = lane & 7;
    const int v    = lane >> 3;
    const int r0   = u;
    const int r1   = u + 8;

    int   jj[7];
    float bias[7];
    bool  jv[7];
#pragma unroll
    for (int m = 0; m < 7; m++) {
        int j = wid * 28 + 4 * m + v;
        jv[m]   = (j < HID);
        jj[m]   = jv[m] ? j : 0;           // clamp keeps reads in-bounds (dup reads broadcast)
        bias[m] = bvec[jj[m]];
    }
    __syncthreads();

    for (int t = 0; t < T_STEPS; t++) {
        // stage x[t, b0:b0+16, :]  (448 contiguous floats)
        const float* gx = x + (size_t)t * (BATCH * IN_DIM) + (size_t)b0 * IN_DIM;
        for (int i = tid; i < BBLK * IN_DIM; i += NTHREADS) {
            int bb = i / IN_DIM;
            int k  = i - bb * IN_DIM;
            sm_x[bb * USTR + k] = gx[i];
        }
        __syncthreads();   // x ready; previous step's h writes visible

        unsigned long long acc0[7], acc1[7];   // packed pairs over (k even, k odd)
#pragma unroll
        for (int m = 0; m < 7; m++) { acc0[m] = 0ull; acc1[m] = 0ull; }

        // ---- input projection: K = 28 -> 7 quads ----
#pragma unroll
        for (int kq = 0; kq < IN_DIM / 4; kq++) {
            ulonglong2 xv0 = *reinterpret_cast<const ulonglong2*>(sm_x + r0 * USTR + kq * 4);
            ulonglong2 xv1 = *reinterpret_cast<const ulonglong2*>(sm_x + r1 * USTR + kq * 4);
#pragma unroll
            for (int m = 0; m < 7; m++) {
                ulonglong2 uv = *reinterpret_cast<const ulonglong2*>(sm_U + jj[m] * USTR + kq * 4);
                fma2(acc0[m], xv0.x, uv.x);
                fma2(acc0[m], xv0.y, uv.y);
                fma2(acc1[m], xv1.x, uv.x);
                fma2(acc1[m], xv1.y, uv.y);
            }
        }

        // ---- recurrent part: K padded to 200 -> 50 quads ----
#pragma unroll 2
        for (int kq = 0; kq < KPAD / 4; kq++) {
            ulonglong2 hv0 = *reinterpret_cast<const ulonglong2*>(sm_h + r0 * HSTR + kq * 4);
            ulonglong2 hv1 = *reinterpret_cast<const ulonglong2*>(sm_h + r1 * HSTR + kq * 4);
#pragma unroll
            for (int m = 0; m < 7; m++) {
                ulonglong2 wv = *reinterpret_cast<const ulonglong2*>(sm_H + jj[m] * HSTR + kq * 4);
                fma2(acc0[m], hv0.x, wv.x);
                fma2(acc0[m], hv0.y, wv.y);
                fma2(acc1[m], hv1.x, wv.x);
                fma2(acc1[m], hv1.y, wv.y);
            }
        }

        __syncthreads();   // all reads of h done before overwrite

#pragma unroll
        for (int m = 0; m < 7; m++) {
            float2 a0 = *reinterpret_cast<float2*>(&acc0[m]);
            float2 a1 = *reinterpret_cast<float2*>(&acc1[m]);
            float h0 = tanhf(a0.x + a0.y + bias[m]);
            float h1 = tanhf(a1.x + a1.y + bias[m]);
            if (jv[m]) {
                sm_h[r0 * HSTR + jj[m]] = h0;
                sm_h[r1 * HSTR + jj[m]] = h1;
            }
        }
    }
    __syncthreads();

    // ---- output projection: out[b][o] = h[b] . A[o] + c[o]  (16 x 10 per block) ----
    if (tid < BBLK * OUT_DIM) {
        int bb = tid / OUT_DIM;
        int o  = tid - bb * OUT_DIM;
        float s = cvec[o];
        const float* hrow = sm_h + bb * HSTR;
        const float* arow = A + o * HID;
#pragma unroll 4
        for (int j = 0; j < HID; j++)
            s += hrow[j] * arow[j];
        out[(b0 + bb) * OUT_DIM + o] = s;
    }
}

extern "C" void kernel_launch(void* const* d_in, const int* in_sizes, int n_in,
                              void* d_out, int out_size)
{
    const float *x = nullptr, *H = nullptr, *U = nullptr, *A = nullptr, *b = nullptr, *c = nullptr;
    for (int i = 0; i < n_in; i++) {
        const float* p = (const float*)d_in[i];
        switch (in_sizes[i]) {
            case T_STEPS * BATCH * IN_DIM: x = p; break;
            case HID * HID:                H = p; break;
            case IN_DIM * HID:             U = p; break;
            case OUT_DIM * HID:            A = p; break;
            case HID:                      b = p; break;
            case OUT_DIM:                  c = p; break;
            default: break;
        }
    }
    float* out = (float*)d_out;

    size_t smem_bytes = SMEM_FLOATS * sizeof(float);   // 205,440 B
    cudaFuncSetAttribute(SimpleRNN_kernel,
                         cudaFuncAttributeMaxDynamicSharedMemorySize, (int)smem_bytes);

    SimpleRNN_kernel<<<NBLOCKS, NTHREADS, smem_bytes>>>(x, H, U, A, b, c, out);
}

// round 11
// speedup vs baseline: 1.1787x; 1.0900x over previous
#include <cuda_runtime.h>

#define T_STEPS 512
#define BATCH   2048
#define IN_DIM  28
#define HID     198
#define OUT_DIM 10

#define BBLK     16
#define NBLOCKS  (BATCH / BBLK)   // 128
#define NTHREADS 512              // 16 warps: 8 j-warps x 2 k-halves

#define KPAD 200                  // recurrent k padded to 200 (50 quads), pad = 0
#define HSTR 204                  // 204 mod 32 = 12 -> 8 row-lanes hit 32 distinct banks
#define USTR 36                   // 36 mod 32 = 4 -> conflict-free

// k-split: half 0 = input proj (7 quads) + recurrent quads [0,22); half 1 = quads [22,50)
#define KQ_SPLIT 22

// shared layout (floats)
#define H_S_OFF   0
#define U_S_OFF   (HID * HSTR)                 // 40392
#define HST_S_OFF (U_S_OFF + HID * USTR)       // 47520
#define X_S_OFF   (HST_S_OFF + BBLK * HSTR)    // 50784
#define RED_S_OFF (X_S_OFF + BBLK * USTR)      // 51360
#define SMEM_FLOATS (RED_S_OFF + 8 * 32 * 14)  // 54944 -> 219,776 B (< 227 KB)

// packed dual-fp32 FMA: d.lo += a.lo*b.lo ; d.hi += a.hi*b.hi
__device__ __forceinline__ void fma2(unsigned long long& d,
                                     unsigned long long a,
                                     unsigned long long b) {
    asm("fma.rn.f32x2 %0, %1, %2, %0;" : "+l"(d) : "l"(a), "l"(b));
}

// branchless fast tanh via __expf (rel err ~1e-7, MUFU.EX2 + MUFU.RCP based)
__device__ __forceinline__ float fast_tanh(float x) {
    float ax = fabsf(x);
    float t  = __expf(-2.0f * ax);
    float r  = __fdividef(1.0f - t, 1.0f + t);
    return copysignf(r, x);
}

// one recurrent k-quad: 2 h-row vectors x 7 W-rows, packed FMAs
__device__ __forceinline__ void rec_quad(
    unsigned long long (&acc0)[7], unsigned long long (&acc1)[7],
    const float* __restrict__ sm_H, const float* __restrict__ sm_h,
    const int (&jj)[7], int r0, int r1, int kq)
{
    ulonglong2 hv0 = *reinterpret_cast<const ulonglong2*>(sm_h + r0 * HSTR + kq * 4);
    ulonglong2 hv1 = *reinterpret_cast<const ulonglong2*>(sm_h + r1 * HSTR + kq * 4);
#pragma unroll
    for (int m = 0; m < 7; m++) {
        ulonglong2 wv = *reinterpret_cast<const ulonglong2*>(sm_H + jj[m] * HSTR + kq * 4);
        fma2(acc0[m], hv0.x, wv.x);
        fma2(acc0[m], hv0.y, wv.y);
        fma2(acc1[m], hv1.x, wv.x);
        fma2(acc1[m], hv1.y, wv.y);
    }
}

__global__ __launch_bounds__(NTHREADS, 1)
void SimpleRNN_kernel(const float* __restrict__ x, const float* __restrict__ H,
                      const float* __restrict__ U, const float* __restrict__ A,
                      const float* __restrict__ bvec, const float* __restrict__ cvec,
                      float* __restrict__ out)
{
    extern __shared__ float sm[];
    float* sm_H   = sm + H_S_OFF;    // [HID][HSTR], k-cols 198..203 zero
    float* sm_U   = sm + U_S_OFF;    // [HID][USTR] transposed U, k-cols 28..35 zero
    float* sm_h   = sm + HST_S_OFF;  // [16][HSTR], pad cols stay zero forever
    float* sm_x   = sm + X_S_OFF;    // [16][USTR]
    float2* sm_red = reinterpret_cast<float2*>(sm + RED_S_OFF);  // [8*32][7]

    const int tid = threadIdx.x;
    const int b0  = blockIdx.x * BBLK;

    // ---- one-time weight staging ----
    for (int i = tid; i < HID * HSTR; i += NTHREADS) {
        int j = i / HSTR, k = i - j * HSTR;
        sm_H[i] = (k < HID) ? H[j * HID + k] : 0.f;
    }
    for (int i = tid; i < HID * USTR; i += NTHREADS) {
        int j = i / USTR, k = i - j * USTR;
        sm_U[i] = (k < IN_DIM) ? U[k * HID + j] : 0.f;
    }
    for (int i = tid; i < BBLK * HSTR; i += NTHREADS)
        sm_h[i] = 0.f;                                 // h0 = 0

    // ---- lane decomposition ----
    // warp: jw = wid>>1 (j-group 0..7), kh = wid&1 (k-half)
    // lane: u = row-lane (0..7), v = j-lane (0..3); thread: rows {u,u+8} x 7 j
    const int wid  = tid >> 5;
    const int lane = tid & 31;
    const int jw   = wid >> 1;
    const int kh   = wid & 1;
    const int u    = lane & 7;
    const int v    = lane >> 3;
    const int r0   = u;
    const int r1   = u + 8;

    int   jj[7];
    float bias[7];
    bool  jv[7];
#pragma unroll
    for (int m = 0; m < 7; m++) {
        int j = jw * 28 + 4 * m + v;
        jv[m]   = (j < HID);
        jj[m]   = jv[m] ? j : 0;          // clamp keeps reads in-bounds
        bias[m] = bvec[jj[m]];
    }
    float2* red = sm_red + (jw * 32 + lane) * 7;
    __syncthreads();

    for (int t = 0; t < T_STEPS; t++) {
        // stage x[t, b0:b0+16, :]  (448 contiguous floats, one per thread)
        const float* gx = x + (size_t)t * (BATCH * IN_DIM) + (size_t)b0 * IN_DIM;
        if (tid < BBLK * IN_DIM) {
            int bb = tid / IN_DIM;
            int k  = tid - bb * IN_DIM;
            sm_x[bb * USTR + k] = gx[tid];
        }
        __syncthreads();   // x ready; previous step's h writes visible

        unsigned long long acc0[7], acc1[7];
#pragma unroll
        for (int m = 0; m < 7; m++) { acc0[m] = 0ull; acc1[m] = 0ull; }

        if (kh == 0) {
            // input projection: K = 28 -> 7 quads
#pragma unroll
            for (int kq = 0; kq < IN_DIM / 4; kq++) {
                ulonglong2 xv0 = *reinterpret_cast<const ulonglong2*>(sm_x + r0 * USTR + kq * 4);
                ulonglong2 xv1 = *reinterpret_cast<const ulonglong2*>(sm_x + r1 * USTR + kq * 4);
#pragma unroll
                for (int m = 0; m < 7; m++) {
                    ulonglong2 uv = *reinterpret_cast<const ulonglong2*>(sm_U + jj[m] * USTR + kq * 4);
                    fma2(acc0[m], xv0.x, uv.x);
                    fma2(acc0[m], xv0.y, uv.y);
                    fma2(acc1[m], xv1.x, uv.x);
                    fma2(acc1[m], xv1.y, uv.y);
                }
            }
            // recurrent quads [0, KQ_SPLIT)
#pragma unroll 2
            for (int kq = 0; kq < KQ_SPLIT; kq++)
                rec_quad(acc0, acc1, sm_H, sm_h, jj, r0, r1, kq);
        } else {
            // recurrent quads [KQ_SPLIT, 50)
#pragma unroll 2
            for (int kq = KQ_SPLIT; kq < KPAD / 4; kq++)
                rec_quad(acc0, acc1, sm_H, sm_h, jj, r0, r1, kq);
        }

        // horizontal sums of packed accumulators
        float s0[7], s1[7];
#pragma unroll
        for (int m = 0; m < 7; m++) {
            float2 a0 = *reinterpret_cast<float2*>(&acc0[m]);
            float2 a1 = *reinterpret_cast<float2*>(&acc1[m]);
            s0[m] = a0.x + a0.y;
            s1[m] = a1.x + a1.y;
        }

        if (kh == 1) {
#pragma unroll
            for (int m = 0; m < 7; m++)
                red[m] = make_float2(s0[m], s1[m]);
        }

        __syncthreads();   // partials visible; all sm_h reads done before overwrite

        if (kh == 0) {
#pragma unroll
            for (int m = 0; m < 7; m++) {
                float2 p  = red[m];
                float h0  = fast_tanh(s0[m] + p.x + bias[m]);
                float h1  = fast_tanh(s1[m] + p.y + bias[m]);
                if (jv[m]) {
                    sm_h[r0 * HSTR + jj[m]] = h0;
                    sm_h[r1 * HSTR + jj[m]] = h1;
                }
            }
        }
    }
    __syncthreads();

    // ---- output projection: out[b][o] = h[b] . A[o] + c[o]  (16 x 10 per block) ----
    if (tid < BBLK * OUT_DIM) {
        int bb = tid / OUT_DIM;
        int o  = tid - bb * OUT_DIM;
        float s = cvec[o];
        const float* hrow = sm_h + bb * HSTR;
        const float* arow = A + o * HID;
#pragma unroll 4
        for (int j = 0; j < HID; j++)
            s += hrow[j] * arow[j];
        out[(b0 + bb) * OUT_DIM + o] = s;
    }
}

extern "C" void kernel_launch(void* const* d_in, const int* in_sizes, int n_in,
                              void* d_out, int out_size)
{
    const float *x = nullptr, *H = nullptr, *U = nullptr, *A = nullptr, *b = nullptr, *c = nullptr;
    for (int i = 0; i < n_in; i++) {
        const float* p = (const float*)d_in[i];
        switch (in_sizes[i]) {
            case T_STEPS * BATCH * IN_DIM: x = p; break;
            case HID * HID:                H = p; break;
            case IN_DIM * HID:             U = p; break;
            case OUT_DIM * HID:            A = p; break;
            case HID:                      b = p; break;
            case OUT_DIM:                  c = p; break;
            default: break;
        }
    }
    float* out = (float*)d_out;

    size_t smem_bytes = SMEM_FLOATS * sizeof(float);   // 219,776 B
    cudaFuncSetAttribute(SimpleRNN_kernel,
                         cudaFuncAttributeMaxDynamicSharedMemorySize, (int)smem_bytes);

    SimpleRNN_kernel<<<NBLOCKS, NTHREADS, smem_bytes>>>(x, H, U, A, b, c, out);
}